// round 15
// baseline (speedup 1.0000x reference)
#include <cuda_runtime.h>
#include <cuda_bf16.h>

#define NLEVELS 16
#define TBL     (1u << 19)
#define NPTS    (64 * 64 * 64)

constexpr double SCALE_ = 1.447269237440378;

__host__ __device__ constexpr int res_of(int l) {
    double r = 16.0;
    for (int i = 0; i < l; ++i) r *= SCALE_;
    return (int)(r + 1e-6);
}

#define ENC_ROW_BYTES 80                      // 64B data + 16B pad (conflict-free)
#define ENC_WARP_BYTES (32 * ENC_ROW_BYTES)   // 2560B per warp
#define W1T_ROW 72                            // bf16 units per row (64 + 8 pad)

__device__ __forceinline__ unsigned smem_u32(const void* p) {
    unsigned a;
    asm("{ .reg .u64 t; cvta.to.shared.u64 t, %1; cvt.u32.u64 %0, t; }"
        : "=r"(a) : "l"(p));
    return a;
}

__global__ __launch_bounds__(256, 3)
void hashgrid_mlp_kernel(const float* __restrict__ pts,
                         const float* __restrict__ table,
                         const float* __restrict__ w1,
                         const float* __restrict__ w2,
                         float* __restrict__ out)
{
    __shared__ __align__(16) unsigned char senc[8 * ENC_WARP_BYTES];  // 20 KB
    __shared__ __nv_bfloat16 sw1t[32 * W1T_ROW];                      // w1^T, 4.5 KB
    __shared__ float sw2[64];
    __shared__ float sacc[256];

    const int tid = threadIdx.x;
    for (int idx = tid; idx < 64 * 32; idx += 256) {
        const int j = idx >> 5, k = idx & 31;
        sw1t[k * W1T_ROW + j] = __float2bfloat16(w1[idx]);
    }
    if (tid < 64) sw2[tid] = w2[tid];
    __syncthreads();

    const int i = blockIdx.x * 256 + tid;
    const int lane = tid & 31, wid = tid >> 5;

    const float px = __ldg(pts + 3 * i + 0);
    const float py = __ldg(pts + 3 * i + 1);
    const float pz = __ldg(pts + 3 * i + 2);

    constexpr int RESA[NLEVELS] = {
        res_of(0),  res_of(1),  res_of(2),  res_of(3),
        res_of(4),  res_of(5),  res_of(6),  res_of(7),
        res_of(8),  res_of(9),  res_of(10), res_of(11),
        res_of(12), res_of(13), res_of(14), res_of(15)
    };

    unsigned char* myrow = senc + wid * ENC_WARP_BYTES + lane * ENC_ROW_BYTES;
    unsigned grp[4];   // 4 levels -> one STS.128

    // ---- gather: 2 levels per iteration, 8 LDG.128 in flight ----
#pragma unroll
    for (int lp = 0; lp < NLEVELS / 2; ++lp) {
        float tx[2], ty[2], tz[2];
        unsigned iA[2][4], iB[2][4];

#pragma unroll
        for (int s = 0; s < 2; ++s) {
            const int l = 2 * lp + s;
            const int res = RESA[l];
            const bool dense =
                ((long long)(res + 1) * (res + 1) * (res + 1) <= (long long)TBL);
            const float fres = (float)res;
            const float x = px * fres, y = py * fres, z = pz * fres;
            const float fx = floorf(x), fy = floorf(y), fz = floorf(z);
            tx[s] = x - fx; ty[s] = y - fy; tz[s] = z - fz;
            const unsigned cx = (unsigned)fx, cy = (unsigned)fy, cz = (unsigned)fz;
#pragma unroll
            for (int c = 0; c < 4; ++c) {
                const unsigned Y = cy + ((c >> 1) & 1u);
                const unsigned Z = cz + (c & 1u);
                if (dense) {
                    const unsigned r1 = (unsigned)(res + 1);
                    const unsigned b = r1 * (Y + r1 * Z);
                    iA[s][c] = (cx + b) & (TBL - 1u);
                    iB[s][c] = (cx + 1u + b) & (TBL - 1u);
                } else {
                    const unsigned h = (Y * 2654435761u) ^ (Z * 805459861u);
                    iA[s][c] = (cx ^ h) & (TBL - 1u);
                    iB[s][c] = ((cx + 1u) ^ h) & (TBL - 1u);
                }
            }
        }

        // 8 primary LDG.128 back-to-back
        float4 v[2][4];
#pragma unroll
        for (int s = 0; s < 2; ++s) {
            const float2* tab = (const float2*)table + (size_t)(2 * lp + s) * TBL;
#pragma unroll
            for (int c = 0; c < 4; ++c)
                v[s][c] = __ldg((const float4*)tab + (iA[s][c] >> 1));
        }

        // predicated fallbacks
        float2 b64[2][4];
        bool cont[2][4];
#pragma unroll
        for (int s = 0; s < 2; ++s) {
            const float2* tab = (const float2*)table + (size_t)(2 * lp + s) * TBL;
#pragma unroll
            for (int c = 0; c < 4; ++c) {
                cont[s][c] = ((iA[s][c] >> 1) == (iB[s][c] >> 1));
                if (!cont[s][c]) b64[s][c] = __ldg(tab + iB[s][c]);
            }
        }

        // combine both levels
#pragma unroll
        for (int s = 0; s < 2; ++s) {
            float e0 = 0.f, e1 = 0.f;
#pragma unroll
            for (int c = 0; c < 4; ++c) {
                const float2 lo = make_float2(v[s][c].x, v[s][c].y);
                const float2 hi = make_float2(v[s][c].z, v[s][c].w);
                const float2 tA = (iA[s][c] & 1u) ? hi : lo;
                const float2 tBc = (iB[s][c] & 1u) ? hi : lo;
                const float2 tB = cont[s][c] ? tBc : b64[s][c];
                const float wyz = (((c >> 1) & 1) ? ty[s] : 1.f - ty[s]) *
                                  ((c & 1) ? tz[s] : 1.f - tz[s]);
                const float wA = (1.f - tx[s]) * wyz;
                const float wB = tx[s] * wyz;
                e0 = fmaf(wA, tA.x, fmaf(wB, tB.x, e0));
                e1 = fmaf(wA, tA.y, fmaf(wB, tB.y, e1));
            }
            const __nv_bfloat162 p = __floats2bfloat162_rn(e0, e1);
            const int l = 2 * lp + s;
            grp[l & 3] = *reinterpret_cast<const unsigned*>(&p);
            if ((l & 3) == 3)
                *reinterpret_cast<uint4*>(myrow + 16 * (l >> 2)) =
                    make_uint4(grp[0], grp[1], grp[2], grp[3]);
        }
    }
    __syncwarp();

    // ---- tensor-core MLP: C[32x64] = A[32x32] @ w1^T, relu, dot w2 ----
    const unsigned encb = smem_u32(senc) + wid * ENC_WARP_BYTES;
    const unsigned w1tb = smem_u32(sw1t);
    const int g = lane >> 2, t = lane & 3;

    unsigned a[2][2][4];
    {
        const int m = lane >> 3;
        const int rown = ((m & 1) << 3) + (lane & 7);
        const int seg = m >> 1;
#pragma unroll
        for (int mt = 0; mt < 2; ++mt)
#pragma unroll
            for (int kt = 0; kt < 2; ++kt) {
                const unsigned addr = encb + (mt * 16 + rown) * ENC_ROW_BYTES
                                    + kt * 32 + seg * 16;
                asm volatile("ldmatrix.sync.aligned.m8n8.x4.shared.b16 "
                             "{%0,%1,%2,%3}, [%4];"
                             : "=r"(a[mt][kt][0]), "=r"(a[mt][kt][1]),
                               "=r"(a[mt][kt][2]), "=r"(a[mt][kt][3])
                             : "r"(addr));
            }
    }

    float acc0 = 0.f, acc1 = 0.f, acc2 = 0.f, acc3 = 0.f;
    const int brow = (lane & 7) + ((lane >> 3) & 1) * 8;

#pragma unroll
    for (int nt = 0; nt < 8; ++nt) {
        unsigned b0[2], b1[2];
#pragma unroll
        for (int kt = 0; kt < 2; ++kt) {
            const unsigned baddr = w1tb + (kt * 16 + brow) * (W1T_ROW * 2) + nt * 16;
            asm volatile("ldmatrix.sync.aligned.m8n8.x2.trans.shared.b16 "
                         "{%0,%1}, [%2];"
                         : "=r"(b0[kt]), "=r"(b1[kt]) : "r"(baddr));
        }
        const float2 w2p = *reinterpret_cast<const float2*>(sw2 + nt * 8 + 2 * t);
#pragma unroll
        for (int mt = 0; mt < 2; ++mt) {
            float c0 = 0.f, c1 = 0.f, c2 = 0.f, c3 = 0.f;
#pragma unroll
            for (int kt = 0; kt < 2; ++kt) {
                asm volatile(
                    "mma.sync.aligned.m16n8k16.row.col.f32.bf16.bf16.f32 "
                    "{%0,%1,%2,%3}, {%4,%5,%6,%7}, {%8,%9}, {%0,%1,%2,%3};"
                    : "+f"(c0), "+f"(c1), "+f"(c2), "+f"(c3)
                    : "r"(a[mt][kt][0]), "r"(a[mt][kt][1]),
                      "r"(a[mt][kt][2]), "r"(a[mt][kt][3]),
                      "r"(b0[kt]), "r"(b1[kt]));
            }
            c0 = fmaxf(c0, 0.f); c1 = fmaxf(c1, 0.f);
            c2 = fmaxf(c2, 0.f); c3 = fmaxf(c3, 0.f);
            if (mt == 0) {
                acc0 = fmaf(c0, w2p.x, fmaf(c1, w2p.y, acc0));
                acc1 = fmaf(c2, w2p.x, fmaf(c3, w2p.y, acc1));
            } else {
                acc2 = fmaf(c0, w2p.x, fmaf(c1, w2p.y, acc2));
                acc3 = fmaf(c2, w2p.x, fmaf(c3, w2p.y, acc3));
            }
        }
    }

#pragma unroll
    for (int s = 1; s < 4; s <<= 1) {
        acc0 += __shfl_xor_sync(~0u, acc0, s);
        acc1 += __shfl_xor_sync(~0u, acc1, s);
        acc2 += __shfl_xor_sync(~0u, acc2, s);
        acc3 += __shfl_xor_sync(~0u, acc3, s);
    }
    if (t == 0) {
        float* sa = sacc + wid * 32;
        sa[g]      = acc0;
        sa[g + 8]  = acc1;
        sa[g + 16] = acc2;
        sa[g + 24] = acc3;
    }
    __syncwarp();

    const float accv = sacc[wid * 32 + lane];
    out[i] = __fdividef(1.f, 1.f + __expf(-accv));
}

extern "C" void kernel_launch(void* const* d_in, const int* in_sizes, int n_in,
                              void* d_out, int out_size)
{
    const float* pts   = (const float*)d_in[0];   // [N,3]
    const float* table = (const float*)d_in[1];   // [16, 2^19, 2]
    const float* w1    = (const float*)d_in[2];   // [64, 32]
    const float* w2    = (const float*)d_in[3];   // [1, 64]
    float* out = (float*)d_out;

    hashgrid_mlp_kernel<<<NPTS / 256, 256>>>(pts, table, w1, w2, out);
}

// round 16
// speedup vs baseline: 1.0879x; 1.0879x over previous
#include <cuda_runtime.h>
#include <cuda_bf16.h>

#define NLEVELS 16
#define TBL     (1u << 19)
#define NPTS    (64 * 64 * 64)

constexpr double SCALE_ = 1.447269237440378;

__host__ __device__ constexpr int res_of(int l) {
    double r = 16.0;
    for (int i = 0; i < l; ++i) r *= SCALE_;
    return (int)(r + 1e-6);
}

#define ENC_ROW_BYTES 80                      // 64B data + 16B pad (conflict-free)
#define ENC_WARP_BYTES (32 * ENC_ROW_BYTES)   // 2560B per warp
#define W1T_ROW 72                            // bf16 units per row (64 + 8 pad)

__device__ __forceinline__ unsigned smem_u32(const void* p) {
    unsigned a;
    asm("{ .reg .u64 t; cvta.to.shared.u64 t, %1; cvt.u32.u64 %0, t; }"
        : "=r"(a) : "l"(p));
    return a;
}

__global__ __launch_bounds__(256, 4)
void hashgrid_mlp_kernel(const float* __restrict__ pts,
                         const float* __restrict__ table,
                         const float* __restrict__ w1,
                         const float* __restrict__ w2,
                         float* __restrict__ out)
{
    __shared__ __align__(16) unsigned char senc[8 * ENC_WARP_BYTES];  // 20 KB
    __shared__ __nv_bfloat16 sw1t[32 * W1T_ROW];                      // w1^T, 4.5 KB
    __shared__ float sw2[64];
    __shared__ float sacc[256];

    const int tid = threadIdx.x;
    // stage w1 transposed: sw1t[k][j] = bf16(w1[j][k])
    for (int idx = tid; idx < 64 * 32; idx += 256) {
        const int j = idx >> 5, k = idx & 31;
        sw1t[k * W1T_ROW + j] = __float2bfloat16(w1[idx]);
    }
    if (tid < 64) sw2[tid] = w2[tid];
    __syncthreads();

    const int i = blockIdx.x * 256 + tid;
    const int lane = tid & 31, wid = tid >> 5;

    const float px = __ldg(pts + 3 * i + 0);
    const float py = __ldg(pts + 3 * i + 1);
    const float pz = __ldg(pts + 3 * i + 2);

    unsigned enc2[NLEVELS];   // bf16x2 per level

    constexpr int RESA[NLEVELS] = {
        res_of(0),  res_of(1),  res_of(2),  res_of(3),
        res_of(4),  res_of(5),  res_of(6),  res_of(7),
        res_of(8),  res_of(9),  res_of(10), res_of(11),
        res_of(12), res_of(13), res_of(14), res_of(15)
    };

#pragma unroll
    for (int l = 0; l < NLEVELS; ++l) {
        const int res = RESA[l];
        const bool dense = ((long long)(res + 1) * (res + 1) * (res + 1) <= (long long)TBL);

        const float fres = (float)res;
        const float x = px * fres, y = py * fres, z = pz * fres;
        const float fx = floorf(x), fy = floorf(y), fz = floorf(z);
        const float tx = x - fx, ty = y - fy, tz = z - fz;
        const unsigned cx = (unsigned)fx, cy = (unsigned)fy, cz = (unsigned)fz;

        const float2* tab = (const float2*)table + (size_t)l * TBL;

        unsigned iA[4], iB[4];
#pragma unroll
        for (int c = 0; c < 4; ++c) {
            const unsigned Y = cy + ((c >> 1) & 1u);
            const unsigned Z = cz + (c & 1u);
            if (dense) {
                const unsigned r1 = (unsigned)(res + 1);
                const unsigned b = r1 * (Y + r1 * Z);
                iA[c] = (cx + b) & (TBL - 1u);
                iB[c] = (cx + 1u + b) & (TBL - 1u);
            } else {
                const unsigned h = (Y * 2654435761u) ^ (Z * 805459861u);
                iA[c] = (cx ^ h) & (TBL - 1u);
                iB[c] = ((cx + 1u) ^ h) & (TBL - 1u);
            }
        }

        // dense (coarse) levels: cache in L1; hash (fine) levels: L2-only (.cg)
        // so fine-level pollution doesn't evict the coarse tables from L1.
        float4 v[4];
#pragma unroll
        for (int c = 0; c < 4; ++c) {
            const float4* p4 = (const float4*)tab + (iA[c] >> 1);
            v[c] = dense ? __ldg(p4) : __ldcg(p4);
        }

        float2 b64[4];
        bool cont[4];
#pragma unroll
        for (int c = 0; c < 4; ++c) {
            cont[c] = ((iA[c] >> 1) == (iB[c] >> 1));
            if (!cont[c]) {
                const float2* p2 = tab + iB[c];
                b64[c] = dense ? __ldg(p2) : __ldcg(p2);
            }
        }

        float e0 = 0.f, e1 = 0.f;
#pragma unroll
        for (int c = 0; c < 4; ++c) {
            const float2 lo = make_float2(v[c].x, v[c].y);
            const float2 hi = make_float2(v[c].z, v[c].w);
            const float2 tA = (iA[c] & 1u) ? hi : lo;
            const float2 tBc = (iB[c] & 1u) ? hi : lo;
            const float2 tB = cont[c] ? tBc : b64[c];
            const float wyz = (((c >> 1) & 1) ? ty : 1.f - ty) *
                              ((c & 1) ? tz : 1.f - tz);
            const float wA = (1.f - tx) * wyz;
            const float wB = tx * wyz;
            e0 = fmaf(wA, tA.x, fmaf(wB, tB.x, e0));
            e1 = fmaf(wA, tA.y, fmaf(wB, tB.y, e1));
        }
        const __nv_bfloat162 p = __floats2bfloat162_rn(e0, e1);
        enc2[l] = *reinterpret_cast<const unsigned*>(&p);
    }

    // ---- write encoding row to smem (4 STS.128, conflict-free at stride 80) ----
    unsigned char* myrow = senc + wid * ENC_WARP_BYTES + lane * ENC_ROW_BYTES;
#pragma unroll
    for (int q = 0; q < 4; ++q) {
        uint4 w = make_uint4(enc2[4 * q + 0], enc2[4 * q + 1],
                             enc2[4 * q + 2], enc2[4 * q + 3]);
        *reinterpret_cast<uint4*>(myrow + 16 * q) = w;
    }
    __syncwarp();

    // ---- tensor-core MLP: C[32x64] = A[32x32] @ w1^T, relu, dot w2 ----
    const unsigned encb = smem_u32(senc) + wid * ENC_WARP_BYTES;
    const unsigned w1tb = smem_u32(sw1t);
    const int g = lane >> 2, t = lane & 3;

    unsigned a[2][2][4];
    {
        const int m = lane >> 3;                 // 0..3
        const int rown = ((m & 1) << 3) + (lane & 7);
        const int seg = m >> 1;                  // 0..1
#pragma unroll
        for (int mt = 0; mt < 2; ++mt)
#pragma unroll
            for (int kt = 0; kt < 2; ++kt) {
                const unsigned addr = encb + (mt * 16 + rown) * ENC_ROW_BYTES
                                    + kt * 32 + seg * 16;
                asm volatile("ldmatrix.sync.aligned.m8n8.x4.shared.b16 "
                             "{%0,%1,%2,%3}, [%4];"
                             : "=r"(a[mt][kt][0]), "=r"(a[mt][kt][1]),
                               "=r"(a[mt][kt][2]), "=r"(a[mt][kt][3])
                             : "r"(addr));
            }
    }

    float acc0 = 0.f, acc1 = 0.f, acc2 = 0.f, acc3 = 0.f;
    const int brow = (lane & 7) + ((lane >> 3) & 1) * 8;   // 0..15 (lanes 0-15 used)

#pragma unroll
    for (int nt = 0; nt < 8; ++nt) {
        unsigned b0[2], b1[2];
#pragma unroll
        for (int kt = 0; kt < 2; ++kt) {
            const unsigned baddr = w1tb + (kt * 16 + brow) * (W1T_ROW * 2) + nt * 16;
            asm volatile("ldmatrix.sync.aligned.m8n8.x2.trans.shared.b16 "
                         "{%0,%1}, [%2];"
                         : "=r"(b0[kt]), "=r"(b1[kt]) : "r"(baddr));
        }
        const float2 w2p = *reinterpret_cast<const float2*>(sw2 + nt * 8 + 2 * t);
#pragma unroll
        for (int mt = 0; mt < 2; ++mt) {
            float c0 = 0.f, c1 = 0.f, c2 = 0.f, c3 = 0.f;
#pragma unroll
            for (int kt = 0; kt < 2; ++kt) {
                asm volatile(
                    "mma.sync.aligned.m16n8k16.row.col.f32.bf16.bf16.f32 "
                    "{%0,%1,%2,%3}, {%4,%5,%6,%7}, {%8,%9}, {%0,%1,%2,%3};"
                    : "+f"(c0), "+f"(c1), "+f"(c2), "+f"(c3)
                    : "r"(a[mt][kt][0]), "r"(a[mt][kt][1]),
                      "r"(a[mt][kt][2]), "r"(a[mt][kt][3]),
                      "r"(b0[kt]), "r"(b1[kt]));
            }
            c0 = fmaxf(c0, 0.f); c1 = fmaxf(c1, 0.f);
            c2 = fmaxf(c2, 0.f); c3 = fmaxf(c3, 0.f);
            if (mt == 0) {
                acc0 = fmaf(c0, w2p.x, fmaf(c1, w2p.y, acc0));   // row g
                acc1 = fmaf(c2, w2p.x, fmaf(c3, w2p.y, acc1));   // row g+8
            } else {
                acc2 = fmaf(c0, w2p.x, fmaf(c1, w2p.y, acc2));   // row 16+g
                acc3 = fmaf(c2, w2p.x, fmaf(c3, w2p.y, acc3));   // row 24+g
            }
        }
    }

#pragma unroll
    for (int s = 1; s < 4; s <<= 1) {
        acc0 += __shfl_xor_sync(~0u, acc0, s);
        acc1 += __shfl_xor_sync(~0u, acc1, s);
        acc2 += __shfl_xor_sync(~0u, acc2, s);
        acc3 += __shfl_xor_sync(~0u, acc3, s);
    }
    if (t == 0) {
        float* sa = sacc + wid * 32;
        sa[g]      = acc0;
        sa[g + 8]  = acc1;
        sa[g + 16] = acc2;
        sa[g + 24] = acc3;
    }
    __syncwarp();

    const float accv = sacc[wid * 32 + lane];
    out[i] = __fdividef(1.f, 1.f + __expf(-accv));
}

extern "C" void kernel_launch(void* const* d_in, const int* in_sizes, int n_in,
                              void* d_out, int out_size)
{
    const float* pts   = (const float*)d_in[0];   // [N,3]
    const float* table = (const float*)d_in[1];   // [16, 2^19, 2]
    const float* w1    = (const float*)d_in[2];   // [64, 32]
    const float* w2    = (const float*)d_in[3];   // [1, 64]
    float* out = (float*)d_out;

    hashgrid_mlp_kernel<<<NPTS / 256, 256>>>(pts, table, w1, w2, out);
}